// round 1
// baseline (speedup 1.0000x reference)
#include <cuda_runtime.h>

#define TPB 128
#define EPSV 1e-5f

// Block-resident GridNet step.
// Each CTA owns one spatial block (bm,bn,bk) and processes 4 batches.
// Per-thread micro-tile: 1 (i) x 2 (j) x 2 (k) outputs -> 27*4 weight regs.
// SMEM holds the 10x10x10 halo block (k padded to 20 words), double-buffered.
// mean/var maintained incrementally: one block reduction of deltas per iter.
__global__ __launch_bounds__(TPB, 2)
void gridnet_kernel(const float* __restrict__ W,
                    const float* __restrict__ Bias,
                    const float* __restrict__ Rscale,
                    const float* __restrict__ X,
                    float* __restrict__ Y)
{
    __shared__ float sv0[2000];        // [10][10][20]
    __shared__ float sv1[2000];
    __shared__ float red[3][8];        // [buffer][warp*2 + {sum,sumsq}]

    const int t    = threadIdx.x;
    const int k2   = t & 3;
    const int j2   = (t >> 2) & 3;
    const int ii   = t >> 4;           // 0..7
    const int lane = t & 31;
    const int wid  = t >> 5;

    const int sb = blockIdx.x >> 2;    // spatial block 0..511
    const int bg = blockIdx.x & 3;     // batch group 0..3
    const int bk = sb & 7, bn = (sb >> 3) & 7, bm = sb >> 6;

    const int gi  = bm * 8 + ii;
    const int gj0 = bn * 8 + 2 * j2;
    const int gk0 = bk * 8 + 2 * k2;
    const int jb  = 2 * j2, kb = 2 * k2;

    // ---- weights, sum-of-weights, bias, residual scale into registers ----
    float w[27][2][2];
    float sumw[2][2] = {{0.f, 0.f}, {0.f, 0.f}};
#pragma unroll
    for (int tap = 0; tap < 27; ++tap) {
#pragma unroll
        for (int jj = 0; jj < 2; ++jj) {
            const float2 wv = *reinterpret_cast<const float2*>(
                W + (((size_t)tap * 64 + gi) * 64 + (gj0 + jj)) * 64 + gk0);
            w[tap][jj][0] = wv.x; w[tap][jj][1] = wv.y;
            sumw[jj][0] += wv.x;  sumw[jj][1] += wv.y;
        }
    }
    float bb[2][2], rs[2][2];
#pragma unroll
    for (int jj = 0; jj < 2; ++jj) {
        const float2 bv = *reinterpret_cast<const float2*>(
            Bias + ((size_t)gi * 64 + gj0 + jj) * 64 + gk0);
        const float2 rv = *reinterpret_cast<const float2*>(
            Rscale + ((size_t)gi * 64 + gj0 + jj) * 64 + gk0);
        bb[jj][0] = bv.x; bb[jj][1] = bv.y;
        rs[jj][0] = rv.x; rs[jj][1] = rv.y;
    }

#pragma unroll 1
    for (int b = bg * 4; b < bg * 4 + 4; ++b) {
        // ---- load padded block (zero halo at domain edges), fold initial sums ----
        const float* Xb = X + (size_t)b * 262144;
        float S = 0.f, S2 = 0.f;
        for (int n = t; n < 1000; n += TPB) {
            const int a = n / 100;
            const int r = n - a * 100;
            const int q = r / 10;
            const int c = r - q * 10;
            const int gm = bm * 8 + a - 1;
            const int gn = bn * 8 + q - 1;
            const int gq = bk * 8 + c - 1;
            float v = 0.f;
            if ((unsigned)gm < 64u && (unsigned)gn < 64u && (unsigned)gq < 64u)
                v = Xb[((size_t)gm * 64 + gn) * 64 + gq];
            const int off = a * 200 + q * 20 + c;
            sv0[off] = v;
            sv1[off] = v;
            S  += v;
            S2 += v * v;
        }
#pragma unroll
        for (int o = 16; o; o >>= 1) {
            S  += __shfl_xor_sync(0xffffffffu, S,  o);
            S2 += __shfl_xor_sync(0xffffffffu, S2, o);
        }
        if (lane == 0) { red[2][wid * 2] = S; red[2][wid * 2 + 1] = S2; }
        __syncthreads();
        S  = red[2][0] + red[2][2] + red[2][4] + red[2][6];
        S2 = red[2][1] + red[2][3] + red[2][5] + red[2][7];

        // current inner values for this thread's 4 outputs
        float cur[2][2];
#pragma unroll
        for (int jj = 0; jj < 2; ++jj)
#pragma unroll
            for (int kk = 0; kk < 2; ++kk)
                cur[jj][kk] = sv0[(ii + 1) * 200 + (jb + 1 + jj) * 20 + (kb + 1 + kk)];

#pragma unroll 2
        for (int it = 0; it < 8; ++it) {
            const float* rd = (it & 1) ? sv1 : sv0;
            float*       wr = (it & 1) ? sv0 : sv1;

            const float mean = S * (1.0f / 1000.0f);
            const float var  = S2 * (1.0f / 1000.0f) - mean * mean;
            const float rstd = rsqrtf(var + EPSV);

            float acc[2][2] = {{0.f, 0.f}, {0.f, 0.f}};
#pragma unroll
            for (int dx = 0; dx < 3; ++dx) {
                float v[4][4];
                const float* rp = rd + (ii + dx) * 200 + jb * 20 + kb;
#pragma unroll
                for (int r = 0; r < 4; ++r) {
                    const float2 p0 = *reinterpret_cast<const float2*>(rp + r * 20);
                    const float2 p1 = *reinterpret_cast<const float2*>(rp + r * 20 + 2);
                    v[r][0] = p0.x; v[r][1] = p0.y; v[r][2] = p1.x; v[r][3] = p1.y;
                }
#pragma unroll
                for (int dy = 0; dy < 3; ++dy)
#pragma unroll
                    for (int dz = 0; dz < 3; ++dz) {
                        const int tap = dx * 9 + dy * 3 + dz;
#pragma unroll
                        for (int jj = 0; jj < 2; ++jj)
#pragma unroll
                            for (int kk = 0; kk < 2; ++kk)
                                acc[jj][kk] = fmaf(v[dy + jj][dz + kk],
                                                   w[tap][jj][kk], acc[jj][kk]);
                    }
            }

            float dS = 0.f, dS2 = 0.f;
#pragma unroll
            for (int jj = 0; jj < 2; ++jj)
#pragma unroll
                for (int kk = 0; kk < 2; ++kk) {
                    const float z = fmaf(-mean, sumw[jj][kk], acc[jj][kk]) * rstd
                                    + bb[jj][kk];
                    const float sil = z * __fdividef(1.0f, 1.0f + __expf(-z));
                    const float old = cur[jj][kk];
                    const float nv  = fmaf(rs[jj][kk], sil, old);
                    cur[jj][kk] = nv;
                    dS  += nv - old;
                    dS2 += fmaf(nv, nv, -old * old);
                    wr[(ii + 1) * 200 + (jb + 1 + jj) * 20 + (kb + 1 + kk)] = nv;
                }
#pragma unroll
            for (int o = 16; o; o >>= 1) {
                dS  += __shfl_xor_sync(0xffffffffu, dS,  o);
                dS2 += __shfl_xor_sync(0xffffffffu, dS2, o);
            }
            const int rb = it & 1;
            if (lane == 0) { red[rb][wid * 2] = dS; red[rb][wid * 2 + 1] = dS2; }
            __syncthreads();
            S  += red[rb][0] + red[rb][2] + red[rb][4] + red[rb][6];
            S2 += red[rb][1] + red[rb][3] + red[rb][5] + red[rb][7];
        }

        // ---- write this thread's 4 final outputs ----
        float* Yb = Y + (size_t)b * 262144;
#pragma unroll
        for (int jj = 0; jj < 2; ++jj) {
            float2 o2;
            o2.x = cur[jj][0];
            o2.y = cur[jj][1];
            *reinterpret_cast<float2*>(Yb + ((size_t)gi * 64 + gj0 + jj) * 64 + gk0) = o2;
        }
        // it=7 barrier already ordered all SMEM reads before next batch's loads.
    }
}

extern "C" void kernel_launch(void* const* d_in, const int* in_sizes, int n_in,
                              void* d_out, int out_size)
{
    const float* W  = (const float*)d_in[0];   // (27,64,64,64)
    const float* Bb = (const float*)d_in[1];   // (64,64,64)
    const float* Rs = (const float*)d_in[2];   // (64,64,64)
    const float* X  = (const float*)d_in[3];   // (16,64,64,64)
    float* Y = (float*)d_out;

    gridnet_kernel<<<2048, TPB>>>(W, Bb, Rs, X, Y);
}

// round 2
// speedup vs baseline: 1.1767x; 1.1767x over previous
#include <cuda_runtime.h>

#define TPB 128
#define EPSV 1e-5f

// Block-resident GridNet step.
// Each CTA owns one spatial block (bm,bn,bk) and processes 4 batches.
// Per-thread micro-tile: 1 (i) x 2 (j) x 2 (k) outputs -> 27*4 weight regs.
// SMEM holds the 10x10x10 halo block (k padded to 20 words), double-buffered.
// mean/var maintained incrementally; the cross-warp combine is deferred to
// after the FMA block of the *next* iteration to shorten the critical path.
__global__ __launch_bounds__(TPB, 3)
void gridnet_kernel(const float* __restrict__ W,
                    const float* __restrict__ Bias,
                    const float* __restrict__ Rscale,
                    const float* __restrict__ X,
                    float* __restrict__ Y)
{
    __shared__ float sv0[2000];        // [10][10][20]
    __shared__ float sv1[2000];
    __shared__ float red[2][8];        // [parity][warp*2 + {sum,sumsq}]

    const int t    = threadIdx.x;
    const int k2   = t & 3;
    const int j2   = (t >> 2) & 3;
    const int ii   = t >> 4;           // 0..7
    const int lane = t & 31;
    const int wid  = t >> 5;

    const int sb = blockIdx.x >> 2;    // spatial block 0..511
    const int bg = blockIdx.x & 3;     // batch group 0..3
    const int bk = sb & 7, bn = (sb >> 3) & 7, bm = sb >> 6;

    const int gi  = bm * 8 + ii;
    const int gj0 = bn * 8 + 2 * j2;
    const int gk0 = bk * 8 + 2 * k2;
    const int jb  = 2 * j2, kb = 2 * k2;

    // ---- weights, sum-of-weights, bias, residual scale into registers ----
    float w[27][2][2];
    float sumw[2][2] = {{0.f, 0.f}, {0.f, 0.f}};
#pragma unroll
    for (int tap = 0; tap < 27; ++tap) {
#pragma unroll
        for (int jj = 0; jj < 2; ++jj) {
            const float2 wv = *reinterpret_cast<const float2*>(
                W + (((size_t)tap * 64 + gi) * 64 + (gj0 + jj)) * 64 + gk0);
            w[tap][jj][0] = wv.x; w[tap][jj][1] = wv.y;
            sumw[jj][0] += wv.x;  sumw[jj][1] += wv.y;
        }
    }
    float bb[2][2], rs[2][2];
#pragma unroll
    for (int jj = 0; jj < 2; ++jj) {
        const float2 bv = *reinterpret_cast<const float2*>(
            Bias + ((size_t)gi * 64 + gj0 + jj) * 64 + gk0);
        const float2 rv = *reinterpret_cast<const float2*>(
            Rscale + ((size_t)gi * 64 + gj0 + jj) * 64 + gk0);
        bb[jj][0] = bv.x; bb[jj][1] = bv.y;
        rs[jj][0] = rv.x; rs[jj][1] = rv.y;
    }

#pragma unroll 1
    for (int b = bg * 4; b < bg * 4 + 4; ++b) {
        // ---- load padded block (zero halo at domain edges), fold initial sums ----
        const float* Xb = X + (size_t)b * 262144;
        float S = 0.f, S2 = 0.f;
        for (int n = t; n < 1000; n += TPB) {
            const int a = n / 100;
            const int r = n - a * 100;
            const int q = r / 10;
            const int c = r - q * 10;
            const int gm = bm * 8 + a - 1;
            const int gn = bn * 8 + q - 1;
            const int gq = bk * 8 + c - 1;
            float v = 0.f;
            if ((unsigned)gm < 64u && (unsigned)gn < 64u && (unsigned)gq < 64u)
                v = Xb[((size_t)gm * 64 + gn) * 64 + gq];
            const int off = a * 200 + q * 20 + c;
            sv0[off] = v;
            sv1[off] = v;
            S  += v;
            S2 += v * v;
        }
#pragma unroll
        for (int o = 16; o; o >>= 1) {
            S  += __shfl_xor_sync(0xffffffffu, S,  o);
            S2 += __shfl_xor_sync(0xffffffffu, S2, o);
        }
        // initial sums act as the "iteration -1" partials (parity 1)
        if (lane == 0) { red[1][wid * 2] = S; red[1][wid * 2 + 1] = S2; }
        __syncthreads();

        // current inner values for this thread's 4 outputs
        float cur[2][2];
#pragma unroll
        for (int jj = 0; jj < 2; ++jj)
#pragma unroll
            for (int kk = 0; kk < 2; ++kk)
                cur[jj][kk] = sv0[(ii + 1) * 200 + (jb + 1 + jj) * 20 + (kb + 1 + kk)];

        S = 0.f; S2 = 0.f;   // running totals, folded in after each acc block

#pragma unroll 2
        for (int it = 0; it < 8; ++it) {
            const float* rd = (it & 1) ? sv1 : sv0;
            float*       wr = (it & 1) ? sv0 : sv1;
            const int    pb = (it + 1) & 1;    // partials written before this iter

            // issue the cross-warp partial loads early (latency hidden by FMAs)
            const float dSs  = (red[pb][0] + red[pb][2]) + (red[pb][4] + red[pb][6]);
            const float dS2s = (red[pb][1] + red[pb][3]) + (red[pb][5] + red[pb][7]);

            float acc[2][2] = {{0.f, 0.f}, {0.f, 0.f}};
#pragma unroll
            for (int dx = 0; dx < 3; ++dx) {
                float v[4][4];
                const float* rp = rd + (ii + dx) * 200 + jb * 20 + kb;
#pragma unroll
                for (int r = 0; r < 4; ++r) {
                    const float2 p0 = *reinterpret_cast<const float2*>(rp + r * 20);
                    const float2 p1 = *reinterpret_cast<const float2*>(rp + r * 20 + 2);
                    v[r][0] = p0.x; v[r][1] = p0.y; v[r][2] = p1.x; v[r][3] = p1.y;
                }
#pragma unroll
                for (int dy = 0; dy < 3; ++dy)
#pragma unroll
                    for (int dz = 0; dz < 3; ++dz) {
                        const int tap = dx * 9 + dy * 3 + dz;
#pragma unroll
                        for (int jj = 0; jj < 2; ++jj)
#pragma unroll
                            for (int kk = 0; kk < 2; ++kk)
                                acc[jj][kk] = fmaf(v[dy + jj][dz + kk],
                                                   w[tap][jj][kk], acc[jj][kk]);
                    }
            }

            // fold in the deferred cross-warp partials; compute stats
            S  += dSs;
            S2 += dS2s;
            const float mean = S * (1.0f / 1000.0f);
            const float var  = S2 * (1.0f / 1000.0f) - mean * mean;
            const float rstd = rsqrtf(var + EPSV);

            // epilogue: silu, residual update, store new values first (so the
            // barrier's STS drain overlaps the shfl reduction chain)
            float nvv[2][2];
#pragma unroll
            for (int jj = 0; jj < 2; ++jj)
#pragma unroll
                for (int kk = 0; kk < 2; ++kk) {
                    const float z = fmaf(-mean, sumw[jj][kk], acc[jj][kk]) * rstd
                                    + bb[jj][kk];
                    const float sil = z * __fdividef(1.0f, 1.0f + __expf(-z));
                    const float nv  = fmaf(rs[jj][kk], sil, cur[jj][kk]);
                    nvv[jj][kk] = nv;
                    wr[(ii + 1) * 200 + (jb + 1 + jj) * 20 + (kb + 1 + kk)] = nv;
                }

            float dS = 0.f, dS2 = 0.f;
#pragma unroll
            for (int jj = 0; jj < 2; ++jj)
#pragma unroll
                for (int kk = 0; kk < 2; ++kk) {
                    const float nv  = nvv[jj][kk];
                    const float old = cur[jj][kk];
                    dS  += nv - old;
                    dS2 += fmaf(nv, nv, -old * old);
                    cur[jj][kk] = nv;
                }
#pragma unroll
            for (int o = 16; o; o >>= 1) {
                dS  += __shfl_xor_sync(0xffffffffu, dS,  o);
                dS2 += __shfl_xor_sync(0xffffffffu, dS2, o);
            }
            const int rb = it & 1;
            if (lane == 0) { red[rb][wid * 2] = dS; red[rb][wid * 2 + 1] = dS2; }
            __syncthreads();
        }

        // ---- write this thread's 4 final outputs ----
        float* Yb = Y + (size_t)b * 262144;
#pragma unroll
        for (int jj = 0; jj < 2; ++jj) {
            float2 o2;
            o2.x = cur[jj][0];
            o2.y = cur[jj][1];
            *reinterpret_cast<float2*>(Yb + ((size_t)gi * 64 + gj0 + jj) * 64 + gk0) = o2;
        }
        // it=7 barrier already ordered all SMEM reads before next batch's loads.
    }
}

extern "C" void kernel_launch(void* const* d_in, const int* in_sizes, int n_in,
                              void* d_out, int out_size)
{
    const float* W  = (const float*)d_in[0];   // (27,64,64,64)
    const float* Bb = (const float*)d_in[1];   // (64,64,64)
    const float* Rs = (const float*)d_in[2];   // (64,64,64)
    const float* X  = (const float*)d_in[3];   // (16,64,64,64)
    float* Y = (float*)d_out;

    gridnet_kernel<<<2048, TPB>>>(W, Bb, Rs, X, Y);
}